// round 3
// baseline (speedup 1.0000x reference)
#include <cuda_runtime.h>
#include <cstdint>

#define B 8192
#define TC 512                 // tile cols
#define TR 128                 // tile rows
#define GX (B / TC)            // 16
#define GY (B / TR)            // 64
#define NBLK (GX * GY)         // 1024

#define NEG_INF __int_as_float(0xff800000)
#define ENC_OFF 0x007FFFFFu    // enc(-inf); shifted so encoded -inf == 0

// Zero-initialized device scratch. enc2(-inf)==0, so zero-init == "-inf";
// the last block re-zeros everything for the next graph replay.
__device__ unsigned g_rowmax[B];
__device__ unsigned g_colmax[B];
__device__ float    g_diag[B];      // written by diagonal tiles every launch
__device__ unsigned g_done;

// Monotone float<->uint encoding (shifted): atomicMax(unsigned) == float max.
__device__ __forceinline__ unsigned enc2(float f) {
    unsigned u = __float_as_uint(f);
    return (u ^ ((unsigned)((int)u >> 31) | 0x80000000u)) - ENC_OFF;
}
__device__ __forceinline__ float dec2(unsigned e) {
    unsigned x = e + ENC_OFF;
    unsigned u = (x & 0x80000000u) ? (x ^ 0x80000000u) : ~x;
    return __uint_as_float(u);
}

template<bool DIAG>
__device__ __forceinline__ void scan_body(const float* __restrict__ sim,
                                          int rowBase, int colBase,
                                          int tx, int ty, float* cm) {
    #pragma unroll 2
    for (int r = ty; r < TR; r += 8) {
        const int grow = rowBase + r;
        const float4* p =
            reinterpret_cast<const float4*>(sim + (size_t)grow * B + colBase) + tx;
        float4 v[4];
        #pragma unroll
        for (int j = 0; j < 4; j++) v[j] = p[j * 32];

        float rmax = NEG_INF;
        #pragma unroll
        for (int j = 0; j < 4; j++) {
            float e0 = v[j].x, e1 = v[j].y, e2 = v[j].z, e3 = v[j].w;
            if (DIAG) {
                const int gc = colBase + j * 128 + tx * 4;
                if (grow == gc + 0) { g_diag[grow] = e0; e0 = NEG_INF; }
                if (grow == gc + 1) { g_diag[grow] = e1; e1 = NEG_INF; }
                if (grow == gc + 2) { g_diag[grow] = e2; e2 = NEG_INF; }
                if (grow == gc + 3) { g_diag[grow] = e3; e3 = NEG_INF; }
            }
            cm[j * 4 + 0] = fmaxf(cm[j * 4 + 0], e0);
            cm[j * 4 + 1] = fmaxf(cm[j * 4 + 1], e1);
            cm[j * 4 + 2] = fmaxf(cm[j * 4 + 2], e2);
            cm[j * 4 + 3] = fmaxf(cm[j * 4 + 3], e3);
            rmax = fmaxf(rmax, fmaxf(fmaxf(e0, e1), fmaxf(e2, e3)));
        }
        #pragma unroll
        for (int o = 16; o > 0; o >>= 1)
            rmax = fmaxf(rmax, __shfl_xor_sync(0xffffffffu, rmax, o));
        if (tx == 0) atomicMax(&g_rowmax[grow], enc2(rmax));
    }
}

__global__ void __launch_bounds__(256) wtl_fused(const float* __restrict__ sim,
                                                 float* __restrict__ out) {
    const int tx = threadIdx.x;            // 0..31
    const int ty = threadIdx.y;            // 0..7
    const int tid = ty * 32 + tx;
    const int colBase = blockIdx.x * TC;
    const int rowBase = blockIdx.y * TR;

    float cm[16];
    #pragma unroll
    for (int k = 0; k < 16; k++) cm[k] = NEG_INF;

    // Diagonal intersects this tile iff by/4 == bx (TR=128, TC=512).
    if ((blockIdx.y >> 2) == blockIdx.x)
        scan_body<true >(sim, rowBase, colBase, tx, ty, cm);
    else
        scan_body<false>(sim, rowBase, colBase, tx, ty, cm);

    // Column-max: fold 8 warp-rows via shared, one RED.MAX per column.
    __shared__ float s_col[8][TC];
    #pragma unroll
    for (int j = 0; j < 4; j++)
        *reinterpret_cast<float4*>(&s_col[ty][j * 128 + tx * 4]) =
            make_float4(cm[j * 4 + 0], cm[j * 4 + 1], cm[j * 4 + 2], cm[j * 4 + 3]);
    __syncthreads();

    #pragma unroll
    for (int c = tid; c < TC; c += 256) {
        float m = s_col[0][c];
        #pragma unroll
        for (int s = 1; s < 8; s++) m = fmaxf(m, s_col[s][c]);
        atomicMax(&g_colmax[colBase + c], enc2(m));
    }

    // ---- completion: last block computes the loss and resets scratch ----
    __shared__ unsigned s_last;
    __threadfence();
    __syncthreads();
    if (tid == 0) s_last = atomicAdd(&g_done, 1u);
    __syncthreads();
    if (s_last != NBLK - 1) return;
    __threadfence();   // acquire: see all other blocks' RED results

    float local = 0.0f;
    #pragma unroll 4
    for (int i = tid; i < B; i += 256) {
        const float rm  = dec2(__ldcg(&g_rowmax[i]));
        const float cx  = dec2(__ldcg(&g_colmax[i]));
        const float pos = __ldcg(&g_diag[i]);

        const float pos_loss = fmaxf(0.2f * pos * pos - 0.7f * pos + 0.5f, 0.0f);
        if (rm + 1.0f > pos)
            local += pos_loss + fmaxf(0.9f * rm * rm - 0.4f * rm + 0.03f, 0.0f);
        if (cx + 1.0f > pos)
            local += pos_loss + fmaxf(0.9f * cx * cx - 0.4f * cx + 0.03f, 0.0f);

        // reset for next graph replay (this thread owns exactly these slots)
        g_rowmax[i] = 0u;
        g_colmax[i] = 0u;
    }

    // deterministic block reduction (fixed tree)
    __shared__ float s_sum[256];
    s_sum[tid] = local;
    __syncthreads();
    #pragma unroll
    for (int s = 128; s > 0; s >>= 1) {
        if (tid < s) s_sum[tid] += s_sum[tid + s];
        __syncthreads();
    }
    if (tid == 0) {
        out[0] = s_sum[0] / (float)B;
        g_done = 0u;
    }
}

extern "C" void kernel_launch(void* const* d_in, const int* in_sizes, int n_in,
                              void* d_out, int out_size) {
    const float* sim = (const float*)d_in[0];
    float* out = (float*)d_out;

    dim3 grid(GX, GY);         // (16, 64)
    dim3 block(32, 8);
    wtl_fused<<<grid, block>>>(sim, out);
}